// round 3
// baseline (speedup 1.0000x reference)
#include <cuda_runtime.h>
#include <math.h>

#define B     16
#define C     48
#define T     96
#define PATCH 12
#define FF    64
#define STEPS 7
#define NF0   (C*T)      // 4608
#define NF1   (C*PATCH)  // 576
#define ALPHA 0.5f
#define EPS   1e-5f

#define SPLIT 3
#define RPB   16
#define NB    (B*PATCH*SPLIT)   // 576 blocks
#define NT    256

// -------- global scratch (no allocations allowed) --------
__device__ float g_xn[B*NF0];
__device__ float g_mu0[NF0], g_rs0[NF0];
__device__ unsigned g_gen;   // barrier generation (monotonic across replays)
__device__ unsigned g_cnt;   // barrier arrive count (auto-wraps via atomicInc)

__device__ __forceinline__ float gelu_exact(float x) {
    return 0.5f * x * (1.0f + erff(x * 0.70710678118654752f));
}

// software grid barrier (sense-reversal; all NB blocks co-resident by launch_bounds)
__device__ __forceinline__ void gridbar() {
    __syncthreads();
    if (threadIdx.x == 0) {
        unsigned gen = *((volatile unsigned*)&g_gen);
        __threadfence();
        unsigned t = atomicInc(&g_cnt, NB - 1u);   // wraps to 0 on last arrival
        if (t == NB - 1u) {
            __threadfence();
            atomicExch(&g_gen, gen + 1u);          // release
        } else {
            while (*((volatile unsigned*)&g_gen) == gen) { }
            __threadfence();
        }
    }
    __syncthreads();
}

__global__ void __launch_bounds__(NT, 4)
k_fused(const float* __restrict__ x,
        const float* __restrict__ g0,  const float* __restrict__ b0,
        const float* __restrict__ g1,  const float* __restrict__ b1,
        const float* __restrict__ g2,  const float* __restrict__ b2,
        const float* __restrict__ Wagg,const float* __restrict__ bagg,
        const float* __restrict__ W1,  const float* __restrict__ bm1,
        const float* __restrict__ W2,  const float* __restrict__ bm2,
        const float* __restrict__ wmsg,const float* __restrict__ bmsg,
        float* __restrict__ out)
{
    __shared__ float smu1[NF1], srs1[NF1];   // BN1 stats (redundant per block)
    __shared__ float srescol[B*C];           // res[:, :, p] column
    __shared__ float st[C];                  // t[b,p,:]
    __shared__ float su[FF*RPB];             // i-part of first layer
    __shared__ float sv[FF*C];               // j-part of first layer
    __shared__ float sw2[FF];
    __shared__ float se[RPB*(C+1)];          // edge scores for this block's rows

    const int tid = threadIdx.x;
    const int blk = blockIdx.x;
    const int bp  = blk / SPLIT, sp = blk % SPLIT;
    const int b   = bp / PATCH,  p  = bp % PATCH;
    const int i0  = sp * RPB;
    const int gid = blk * NT + tid;

    // ---------- init phase 1: BN0 stats (distributed across grid) ----------
    if (gid < NF0) {
        float v[B]; float s = 0.f;
        #pragma unroll
        for (int bb = 0; bb < B; bb++) { v[bb] = x[bb*NF0 + gid]; s += v[bb]; }
        float mu = s * (1.0f / B), s2 = 0.f;
        #pragma unroll
        for (int bb = 0; bb < B; bb++) { float d = v[bb] - mu; s2 += d*d; }
        g_mu0[gid] = mu;
        g_rs0[gid] = rsqrtf(s2 * (1.0f / B) + EPS);
    }
    if (tid < FF) sw2[tid] = W2[tid];
    gridbar();

    // ---------- init phase 2: apply BN0 -> g_xn; write "first" into out ----------
    if (gid < B*NF0) {
        int f = gid % NF0;
        float v = (x[gid] - g_mu0[f]) * g_rs0[f] * g0[f] + b0[f];
        g_xn[gid] = v;
        if ((f % T) < PATCH) out[gid] = v;   // first = xn[:,:,:PATCH]
    }
    gridbar();

    const float bm2v = bm2[0];
    const float wm = wmsg[0], bmv = bmsg[0];

    for (int s = 0; s < STEPS; s++) {
        // ---- A: BN1 stats over batch of prev (out segment s), all 576 features ----
        for (int f = tid; f < NF1; f += NT) {
            int c = f / PATCH, pp = f % PATCH;
            const float* base = out + c*T + s*PATCH + pp;   // stride NF0 over batch
            float v[B]; float sum = 0.f;
            #pragma unroll
            for (int bb = 0; bb < B; bb++) { v[bb] = base[bb*NF0]; sum += v[bb]; }
            float mu = sum * (1.0f / B), s2 = 0.f;
            #pragma unroll
            for (int bb = 0; bb < B; bb++) { float d = v[bb] - mu; s2 += d*d; }
            smu1[f] = mu;
            srs1[f] = rsqrtf(s2 * (1.0f / B) + EPS);
        }
        __syncthreads();

        // ---- B: res[:, :, p] column for ALL (b', c) ----
        for (int r = tid; r < B*C; r += NT) {
            int bb = r / C, c = r % C;
            const float* prow = out + bb*NF0 + c*T + s*PATCH;
            float a = bagg[p];
            #pragma unroll
            for (int k = 0; k < PATCH; k++) {
                int f = c*PATCH + k;
                float inv = fmaf((prow[k] - smu1[f]) * srs1[f], g1[f], b1[f]);
                a = fmaf(inv, Wagg[p*PATCH + k], a);
            }
            float xw = g_xn[bb*NF0 + c*T + PATCH + s*PATCH + p];
            srescol[r] = gelu_exact(a) + xw;
        }
        __syncthreads();

        // ---- C: BN2 stats for features (c, p) over batch; st = BN2(res)[b, :, p] ----
        if (tid < C) {
            int c = tid, f = c*PATCH + p;
            float sum = 0.f;
            #pragma unroll
            for (int bb = 0; bb < B; bb++) sum += srescol[bb*C + c];
            float mu = sum * (1.0f / B), s2 = 0.f;
            #pragma unroll
            for (int bb = 0; bb < B; bb++) { float d = srescol[bb*C + c] - mu; s2 += d*d; }
            float rs = rsqrtf(s2 * (1.0f / B) + EPS);
            st[c] = fmaf((srescol[b*C + c] - mu) * rs, g2[f], b2[f]);
        }
        __syncthreads();

        // ---- D: first-layer partials ----
        for (int idx = tid; idx < FF*RPB; idx += NT) {
            int f = idx / RPB, il = idx % RPB;
            su[idx] = fmaf(st[i0 + il], W1[2*f], bm1[f]);
        }
        for (int idx = tid; idx < FF*C; idx += NT) {
            int f = idx / C, j = idx % C;
            sv[idx] = st[j] * W1[2*f + 1];
        }
        __syncthreads();

        // ---- E: e[il][j] = bm2 + sum_f w2[f]*gelu(u+v) — 3 j's per thread, shared il ----
        {
            int il = tid >> 4, jb = tid & 15;
            float acc0 = bm2v, acc1 = bm2v, acc2 = bm2v;
            #pragma unroll 4
            for (int f = 0; f < FF; f++) {
                float u  = su[f*RPB + il];
                float w2f = sw2[f];
                acc0 = fmaf(w2f, gelu_exact(u + sv[f*C + jb     ]), acc0);
                acc1 = fmaf(w2f, gelu_exact(u + sv[f*C + jb + 16]), acc1);
                acc2 = fmaf(w2f, gelu_exact(u + sv[f*C + jb + 32]), acc2);
            }
            se[il*(C+1) + jb     ] = acc0;
            se[il*(C+1) + jb + 16] = acc1;
            se[il*(C+1) + jb + 32] = acc2;
        }
        __syncthreads();

        // ---- F: per-row top-3 (lower index wins ties), softmax, message, write out ----
        {
            int w = tid >> 5, lane = tid & 31;
            #pragma unroll
            for (int rr = 0; rr < 2; rr++) {
                int il = w*2 + rr;
                float va = se[il*(C+1) + lane];
                int   ja = lane;
                int   jb2 = lane + 32;
                float vb = (jb2 < C) ? se[il*(C+1) + jb2] : -3.4e38f;

                float topv[3]; int topj[3];
                #pragma unroll
                for (int k = 0; k < 3; k++) {
                    bool ta = (va > vb) || (va == vb && ja < jb2);
                    float v = ta ? va : vb;
                    int   j = ta ? ja : jb2;
                    #pragma unroll
                    for (int off = 16; off; off >>= 1) {
                        float ov = __shfl_xor_sync(0xffffffffu, v, off);
                        int   oj = __shfl_xor_sync(0xffffffffu, j, off);
                        if (ov > v || (ov == v && oj < j)) { v = ov; j = oj; }
                    }
                    topv[k] = v; topj[k] = j;
                    if (j == ja)  va = -3.4e38f;
                    if (j == jb2) vb = -3.4e38f;
                }
                if (lane == 0) {
                    float m  = topv[0];
                    float e0 = expf(topv[0] - m), e1 = expf(topv[1] - m), e2 = expf(topv[2] - m);
                    float dn = e0 + e1 + e2;
                    float m0 = fmaf(st[topj[0]], wm, bmv);
                    float m1 = fmaf(st[topj[1]], wm, bmv);
                    float m2 = fmaf(st[topj[2]], wm, bmv);
                    float znew = (e0*m0 + e1*m1 + e2*m2) / dn;
                    int i = i0 + il;
                    float resv = srescol[b*C + i];
                    out[(b*C + i)*T + (s+1)*PATCH + p] = fmaf(ALPHA, znew, resv);
                }
            }
        }

        if (s != STEPS - 1) gridbar();   // next step reads out[s+1] written grid-wide
    }
}

extern "C" void kernel_launch(void* const* d_in, const int* in_sizes, int n_in,
                              void* d_out, int out_size) {
    const float* x    = (const float*)d_in[0];
    const float* g0   = (const float*)d_in[1];
    const float* b0   = (const float*)d_in[2];
    const float* g1   = (const float*)d_in[3];
    const float* b1   = (const float*)d_in[4];
    const float* g2   = (const float*)d_in[5];
    const float* b2   = (const float*)d_in[6];
    const float* Wagg = (const float*)d_in[7];
    const float* bagg = (const float*)d_in[8];
    const float* W1   = (const float*)d_in[9];
    const float* bm1  = (const float*)d_in[10];
    const float* W2   = (const float*)d_in[11];
    const float* bm2  = (const float*)d_in[12];
    const float* wmsg = (const float*)d_in[13];
    const float* bmsg = (const float*)d_in[14];
    float* out = (float*)d_out;

    k_fused<<<NB, NT>>>(x, g0, b0, g1, b1, g2, b2, Wagg, bagg,
                        W1, bm1, W2, bm2, wmsg, bmsg, out);
}

// round 4
// speedup vs baseline: 1.0419x; 1.0419x over previous
#include <cuda_runtime.h>
#include <math.h>

#define B     16
#define C     48
#define T     96
#define PATCH 12
#define FF    64
#define STEPS 7
#define NF0   (C*T)      // 4608
#define NF1   (C*PATCH)  // 576
#define ALPHA 0.5f
#define EPS   1e-5f

#define SPLIT 3
#define RPB   16
#define NB    (B*PATCH*SPLIT)   // 576 blocks
#define NT    256

// -------- global scratch (no allocations allowed) --------
__device__ float g_xn[B*NF0];
__device__ float g_mu0[NF0], g_rs0[NF0];
__device__ unsigned g_gen;
__device__ unsigned g_cnt;

// Fast exact-accuracy GELU: Abramowitz-Stegun 7.1.26 erf (max abs err 1.5e-7).
// erf(z) = 1 - P(t)*exp(-z^2), t = 1/(1+0.3275911 z), z >= 0
// gelu(x) = 0.5x(1 + erf(x/sqrt2)) = 0.5x + 0.5|x| * erf(|x|/sqrt2)
__device__ __forceinline__ float gelu_fast(float x) {
    float ax = fabsf(x);
    float z  = ax * 0.70710678118654752f;
    float d  = fmaf(0.3275911f, z, 1.0f);
    float t;
    asm("rcp.approx.f32 %0, %1;" : "=f"(t) : "f"(d));
    float P  = fmaf(1.061405429f, t, -1.453152027f);
    P = fmaf(P, t, 1.421413741f);
    P = fmaf(P, t, -0.284496736f);
    P = fmaf(P, t, 0.254829592f);
    P = P * t;
    float a2 = z * z * (-1.4426950408889634f);   // -z^2 * log2(e)
    float E;
    asm("ex2.approx.f32 %0, %1;" : "=f"(E) : "f"(a2));
    float r = fmaf(-P, E, 1.0f);                 // erf(z), z >= 0
    return fmaf(0.5f * ax, r, 0.5f * x);
}

// software grid barrier (sense-reversal; all NB blocks co-resident by launch_bounds)
__device__ __forceinline__ void gridbar() {
    __syncthreads();
    if (threadIdx.x == 0) {
        unsigned gen = *((volatile unsigned*)&g_gen);
        __threadfence();
        unsigned t = atomicInc(&g_cnt, NB - 1u);   // wraps to 0 on last arrival
        if (t == NB - 1u) {
            __threadfence();
            atomicExch(&g_gen, gen + 1u);          // release
        } else {
            while (*((volatile unsigned*)&g_gen) == gen) { }
            __threadfence();
        }
    }
    __syncthreads();
}

__global__ void __launch_bounds__(NT, 4)
k_fused(const float* __restrict__ x,
        const float* __restrict__ g0,  const float* __restrict__ b0,
        const float* __restrict__ g1,  const float* __restrict__ b1,
        const float* __restrict__ g2,  const float* __restrict__ b2,
        const float* __restrict__ Wagg,const float* __restrict__ bagg,
        const float* __restrict__ W1,  const float* __restrict__ bm1,
        const float* __restrict__ W2,  const float* __restrict__ bm2,
        const float* __restrict__ wmsg,const float* __restrict__ bmsg,
        float* __restrict__ out)
{
    __shared__ float smu1[NF1], srs1[NF1];
    __shared__ float srescol[B*C];
    __shared__ float st[C];
    __shared__ float su[FF*RPB];
    __shared__ float sv[FF*C];
    __shared__ float sw2[FF];
    __shared__ float se[RPB*(C+1)];

    const int tid = threadIdx.x;
    const int blk = blockIdx.x;
    const int bp  = blk / SPLIT, sp = blk % SPLIT;
    const int b   = bp / PATCH,  p  = bp % PATCH;
    const int i0  = sp * RPB;
    const int gid = blk * NT + tid;

    // ---------- init phase 1: BN0 stats ----------
    if (gid < NF0) {
        float v[B]; float s = 0.f;
        #pragma unroll
        for (int bb = 0; bb < B; bb++) { v[bb] = x[bb*NF0 + gid]; s += v[bb]; }
        float mu = s * (1.0f / B), s2 = 0.f;
        #pragma unroll
        for (int bb = 0; bb < B; bb++) { float d = v[bb] - mu; s2 += d*d; }
        g_mu0[gid] = mu;
        g_rs0[gid] = rsqrtf(s2 * (1.0f / B) + EPS);
    }
    if (tid < FF) sw2[tid] = W2[tid];
    gridbar();

    // ---------- init phase 2: apply BN0 -> g_xn; write "first" ----------
    if (gid < B*NF0) {
        int f = gid % NF0;
        float v = (x[gid] - g_mu0[f]) * g_rs0[f] * g0[f] + b0[f];
        g_xn[gid] = v;
        if ((f % T) < PATCH) out[gid] = v;
    }
    gridbar();

    const float bm2v = bm2[0];
    const float wm = wmsg[0], bmv = bmsg[0];

    for (int s = 0; s < STEPS; s++) {
        // ---- A: BN1 stats over batch (out segment s), all 576 features ----
        for (int f = tid; f < NF1; f += NT) {
            int c = f / PATCH, pp = f % PATCH;
            const float* base = out + c*T + s*PATCH + pp;
            float v[B]; float sum = 0.f;
            #pragma unroll
            for (int bb = 0; bb < B; bb++) { v[bb] = base[bb*NF0]; sum += v[bb]; }
            float mu = sum * (1.0f / B), s2 = 0.f;
            #pragma unroll
            for (int bb = 0; bb < B; bb++) { float d = v[bb] - mu; s2 += d*d; }
            smu1[f] = mu;
            srs1[f] = rsqrtf(s2 * (1.0f / B) + EPS);
        }
        __syncthreads();

        // ---- B: res[:, :, p] column for ALL (b', c) ----
        for (int r = tid; r < B*C; r += NT) {
            int bb = r / C, c = r % C;
            const float* prow = out + bb*NF0 + c*T + s*PATCH;
            float a = bagg[p];
            #pragma unroll
            for (int k = 0; k < PATCH; k++) {
                int f = c*PATCH + k;
                float inv = fmaf((prow[k] - smu1[f]) * srs1[f], g1[f], b1[f]);
                a = fmaf(inv, Wagg[p*PATCH + k], a);
            }
            float xw = g_xn[bb*NF0 + c*T + PATCH + s*PATCH + p];
            srescol[r] = gelu_fast(a) + xw;
        }
        __syncthreads();

        // ---- C: BN2 stats for (c, p) over batch; st = BN2(res)[b, :, p] ----
        if (tid < C) {
            int c = tid, f = c*PATCH + p;
            float sum = 0.f;
            #pragma unroll
            for (int bb = 0; bb < B; bb++) sum += srescol[bb*C + c];
            float mu = sum * (1.0f / B), s2 = 0.f;
            #pragma unroll
            for (int bb = 0; bb < B; bb++) { float d = srescol[bb*C + c] - mu; s2 += d*d; }
            float rs = rsqrtf(s2 * (1.0f / B) + EPS);
            st[c] = fmaf((srescol[b*C + c] - mu) * rs, g2[f], b2[f]);
        }
        __syncthreads();

        // ---- D: first-layer partials ----
        for (int idx = tid; idx < FF*RPB; idx += NT) {
            int f = idx / RPB, il = idx % RPB;
            su[idx] = fmaf(st[i0 + il], W1[2*f], bm1[f]);
        }
        for (int idx = tid; idx < FF*C; idx += NT) {
            int f = idx / C, j = idx % C;
            sv[idx] = st[j] * W1[2*f + 1];
        }
        __syncthreads();

        // ---- E: e[il][j] = bm2 + sum_f w2[f]*gelu(u+v) ----
        {
            int il = tid >> 4, jb = tid & 15;
            float acc0 = bm2v, acc1 = bm2v, acc2 = bm2v;
            #pragma unroll 4
            for (int f = 0; f < FF; f++) {
                float u   = su[f*RPB + il];
                float w2f = sw2[f];
                acc0 = fmaf(w2f, gelu_fast(u + sv[f*C + jb     ]), acc0);
                acc1 = fmaf(w2f, gelu_fast(u + sv[f*C + jb + 16]), acc1);
                acc2 = fmaf(w2f, gelu_fast(u + sv[f*C + jb + 32]), acc2);
            }
            se[il*(C+1) + jb     ] = acc0;
            se[il*(C+1) + jb + 16] = acc1;
            se[il*(C+1) + jb + 32] = acc2;
        }
        __syncthreads();

        // ---- F: per-row top-3 (ties -> lower index), softmax, message, write ----
        {
            int w = tid >> 5, lane = tid & 31;
            #pragma unroll
            for (int rr = 0; rr < 2; rr++) {
                int il = w*2 + rr;
                float va = se[il*(C+1) + lane];
                int   ja = lane;
                int   jb2 = lane + 32;
                float vb = (jb2 < C) ? se[il*(C+1) + jb2] : -3.4e38f;

                float topv[3]; int topj[3];
                #pragma unroll
                for (int k = 0; k < 3; k++) {
                    bool ta = (va > vb) || (va == vb && ja < jb2);
                    float v = ta ? va : vb;
                    int   j = ta ? ja : jb2;
                    #pragma unroll
                    for (int off = 16; off; off >>= 1) {
                        float ov = __shfl_xor_sync(0xffffffffu, v, off);
                        int   oj = __shfl_xor_sync(0xffffffffu, j, off);
                        if (ov > v || (ov == v && oj < j)) { v = ov; j = oj; }
                    }
                    topv[k] = v; topj[k] = j;
                    if (j == ja)  va = -3.4e38f;
                    if (j == jb2) vb = -3.4e38f;
                }
                if (lane == 0) {
                    float m  = topv[0];
                    float e0 = expf(topv[0] - m), e1 = expf(topv[1] - m), e2 = expf(topv[2] - m);
                    float dn = e0 + e1 + e2;
                    float m0 = fmaf(st[topj[0]], wm, bmv);
                    float m1 = fmaf(st[topj[1]], wm, bmv);
                    float m2 = fmaf(st[topj[2]], wm, bmv);
                    float znew = (e0*m0 + e1*m1 + e2*m2) / dn;
                    int i = i0 + il;
                    float resv = srescol[b*C + i];
                    out[(b*C + i)*T + (s+1)*PATCH + p] = fmaf(ALPHA, znew, resv);
                }
            }
        }

        if (s != STEPS - 1) gridbar();
    }
}

extern "C" void kernel_launch(void* const* d_in, const int* in_sizes, int n_in,
                              void* d_out, int out_size) {
    const float* x    = (const float*)d_in[0];
    const float* g0   = (const float*)d_in[1];
    const float* b0   = (const float*)d_in[2];
    const float* g1   = (const float*)d_in[3];
    const float* b1   = (const float*)d_in[4];
    const float* g2   = (const float*)d_in[5];
    const float* b2   = (const float*)d_in[6];
    const float* Wagg = (const float*)d_in[7];
    const float* bagg = (const float*)d_in[8];
    const float* W1   = (const float*)d_in[9];
    const float* bm1  = (const float*)d_in[10];
    const float* W2   = (const float*)d_in[11];
    const float* bm2  = (const float*)d_in[12];
    const float* wmsg = (const float*)d_in[13];
    const float* bmsg = (const float*)d_in[14];
    float* out = (float*)d_out;

    k_fused<<<NB, NT>>>(x, g0, b0, g1, b1, g2, b2, Wagg, bagg,
                        W1, bm1, W2, bm2, wmsg, bmsg, out);
}